// round 1
// baseline (speedup 1.0000x reference)
#include <cuda_runtime.h>

// ---------------------------------------------------------------------------
// LIIF sampler, fully fused: gather (nearest grid-sample + rel feats + rgb_std)
// + 5-layer MLP (71->256->256->256->256->3), fp32 FFMA baseline.
//
// Layout per CTA: 64 query points, 256 threads.
//   smem hA/hB : activations, [K][64] (k-major), ping-pong between layers
//   smem wbuf  : 32x256 W chunk staged from global
//   GEMM: thread (tm=tid>>5, tn=tid&31) owns 8 points x 8 neurons (64 fp32 acc)
// ---------------------------------------------------------------------------

#define HQv 384
#define WQv 384
#define HFv 48
#define WFv 48
#define CCv 64
#define HIDv 256
#define MT  64      // points per block
#define NTH 256

// dynamic smem partition (floats)
#define HA_OFF   0
#define HB_OFF   (HIDv * MT)                 // 16384
#define WB_OFF   (2 * HIDv * MT)             // 32768
#define SIY_OFF  (2 * HIDv * MT + 32 * 256)  // 40960
#define SMEM_FLOATS (SIY_OFF + 3 * MT)
#define SMEM_BYTES  (SMEM_FLOATS * 4)

__device__ __forceinline__ void mlp_layer(
    const float* __restrict__ W, const float* __restrict__ bias,
    const float* in, float* outb, float* wbuf, int K, int tid, bool do_relu)
{
    const int tn = tid & 31;
    const int tm = tid >> 5;
    float acc[8][8];
#pragma unroll
    for (int i = 0; i < 8; i++)
#pragma unroll
        for (int j = 0; j < 8; j++) acc[i][j] = 0.0f;

    for (int kc = 0; kc < K; kc += 32) {
        const int kl = min(32, K - kc);
        // stage W rows [kc, kc+kl) -> wbuf (contiguous in global, row length 256)
        {
            const float4* src = (const float4*)(W + (size_t)kc * 256);
            float4* dst = (float4*)wbuf;
            const int n4 = kl * 64;
            for (int idx = tid; idx < n4; idx += NTH) dst[idx] = src[idx];
        }
        __syncthreads();

        if (kl == 32) {
#pragma unroll 8
            for (int k = 0; k < 32; k++) {
                const float4 a0 = *(const float4*)(in + (kc + k) * MT + tm * 8);
                const float4 a1 = *(const float4*)(in + (kc + k) * MT + tm * 8 + 4);
                const float4 w0 = *(const float4*)(wbuf + k * 256 + tn * 8);
                const float4 w1 = *(const float4*)(wbuf + k * 256 + tn * 8 + 4);
                const float a[8] = {a0.x, a0.y, a0.z, a0.w, a1.x, a1.y, a1.z, a1.w};
                const float w[8] = {w0.x, w0.y, w0.z, w0.w, w1.x, w1.y, w1.z, w1.w};
#pragma unroll
                for (int i = 0; i < 8; i++)
#pragma unroll
                    for (int j = 0; j < 8; j++)
                        acc[i][j] = fmaf(a[i], w[j], acc[i][j]);
            }
        } else {
            for (int k = 0; k < kl; k++) {
                const float4 a0 = *(const float4*)(in + (kc + k) * MT + tm * 8);
                const float4 a1 = *(const float4*)(in + (kc + k) * MT + tm * 8 + 4);
                const float4 w0 = *(const float4*)(wbuf + k * 256 + tn * 8);
                const float4 w1 = *(const float4*)(wbuf + k * 256 + tn * 8 + 4);
                const float a[8] = {a0.x, a0.y, a0.z, a0.w, a1.x, a1.y, a1.z, a1.w};
                const float w[8] = {w0.x, w0.y, w0.z, w0.w, w1.x, w1.y, w1.z, w1.w};
#pragma unroll
                for (int i = 0; i < 8; i++)
#pragma unroll
                    for (int j = 0; j < 8; j++)
                        acc[i][j] = fmaf(a[i], w[j], acc[i][j]);
            }
        }
        __syncthreads();
    }

    float bv[8];
#pragma unroll
    for (int j = 0; j < 8; j++) bv[j] = bias[tn * 8 + j];
#pragma unroll
    for (int j = 0; j < 8; j++)
#pragma unroll
        for (int i = 0; i < 8; i++) {
            float v = acc[i][j] + bv[j];
            if (do_relu) v = fmaxf(v, 0.0f);
            outb[(tn * 8 + j) * MT + tm * 8 + i] = v;
        }
    __syncthreads();
}

__global__ __launch_bounds__(NTH, 1)
void liif_fused_kernel(
    const float* __restrict__ x, const float* __restrict__ coord,
    const float* __restrict__ cell, const float* __restrict__ lr,
    const float* __restrict__ W0, const float* __restrict__ b0,
    const float* __restrict__ W1, const float* __restrict__ b1,
    const float* __restrict__ W2, const float* __restrict__ b2,
    const float* __restrict__ W3, const float* __restrict__ b3,
    const float* __restrict__ W4, const float* __restrict__ b4,
    float* __restrict__ out, int P)
{
    extern __shared__ float smem[];
    float* hA = smem + HA_OFF;
    float* hB = smem + HB_OFF;
    float* wbuf = smem + WB_OFF;
    int* s_iy = (int*)(smem + SIY_OFF);
    int* s_ix = s_iy + MT;
    int* s_val = s_ix + MT;

    const int tid = threadIdx.x;
    const int p0 = blockIdx.x * MT;

    // ---- Phase 1: per-point scalar features (threads 0..63) ----
    if (tid < MT) {
        const int p = tid;
        const int gp = p0 + p;
        if (gp < P) {
            const int b = gp / (HQv * WQv);
            const int rem = gp % (HQv * WQv);
            const int yq = rem / WQv;
            const int xq = rem % WQv;
            const float gy = coord[((size_t)(b * HQv + yq) * WQv + xq) * 2 + 0];
            const float gx = coord[((size_t)(b * HQv + yq) * WQv + xq) * 2 + 1];

            // nearest index, round-half-even, align_corners=False
            float tx = __fmul_rn(__fadd_rn(__fmul_rn(__fadd_rn(gx, 1.0f), (float)WFv), -1.0f), 0.5f);
            float ty = __fmul_rn(__fadd_rn(__fmul_rn(__fadd_rn(gy, 1.0f), (float)HFv), -1.0f), 0.5f);
            const int ixn = (int)rintf(tx);
            const int iyn = (int)rintf(ty);
            const bool valid = (ixn >= 0) && (ixn < WFv) && (iyn >= 0) && (iyn < HFv);
            const int ixc = min(max(ixn, 0), WFv - 1);
            const int iyc = min(max(iyn, 0), HFv - 1);
            s_iy[p] = iyc; s_ix[p] = ixc; s_val[p] = valid ? 1 : 0;

            float qy = 0.0f, qx = 0.0f;
            if (valid) {
                qy = __fadd_rn(__fdiv_rn(__fadd_rn(__fmul_rn(2.0f, (float)iyc), 1.0f), (float)HFv), -1.0f);
                qx = __fadd_rn(__fdiv_rn(__fadd_rn(__fmul_rn(2.0f, (float)ixc), 1.0f), (float)WFv), -1.0f);
            }
            hA[64 * MT + p] = __fmul_rn(__fadd_rn(gy, -qy), (float)HFv);
            hA[65 * MT + p] = __fmul_rn(__fadd_rn(gx, -qx), (float)WFv);
            hA[66 * MT + p] = __fmul_rn(cell[b * 2 + 0], (float)HFv);
            hA[67 * MT + p] = __fmul_rn(cell[b * 2 + 1], (float)WFv);

            // rgb_std over 4 diagonally shifted nearest LR samples (always valid after clip)
            const float rx = 1.0f / (float)HFv;
            const float ry = 1.0f / (float)WFv;
            const float lo = -1.0f + 1e-6f, hi = 1.0f - 1e-6f;
            float s[3][4];
            int j = 0;
#pragma unroll
            for (int a = 0; a < 2; a++) {
#pragma unroll
                for (int c2 = 0; c2 < 2; c2++) {
                    const float vx = a ? 1.0f : -1.0f;
                    const float vy = c2 ? 1.0f : -1.0f;
                    float cy = __fadd_rn(__fadd_rn(gy, __fmul_rn(vx, rx)), 1e-6f);
                    float cx = __fadd_rn(__fadd_rn(gx, __fmul_rn(vy, ry)), 1e-6f);
                    cy = fminf(fmaxf(cy, lo), hi);
                    cx = fminf(fmaxf(cx, lo), hi);
                    float fx = __fmul_rn(__fadd_rn(__fmul_rn(__fadd_rn(cx, 1.0f), (float)WFv), -1.0f), 0.5f);
                    float fy = __fmul_rn(__fadd_rn(__fmul_rn(__fadd_rn(cy, 1.0f), (float)HFv), -1.0f), 0.5f);
                    int jx = (int)rintf(fx);
                    int jy = (int)rintf(fy);
                    jx = min(max(jx, 0), WFv - 1);
                    jy = min(max(jy, 0), HFv - 1);
#pragma unroll
                    for (int ch = 0; ch < 3; ch++)
                        s[ch][j] = lr[((size_t)(b * 3 + ch) * HFv + jy) * WFv + jx];
                    j++;
                }
            }
#pragma unroll
            for (int ch = 0; ch < 3; ch++) {
                const float m = 0.25f * (s[ch][0] + s[ch][1] + s[ch][2] + s[ch][3]);
                float v = 0.0f;
#pragma unroll
                for (int q = 0; q < 4; q++) { const float d = s[ch][q] - m; v += d * d; }
                hA[(68 + ch) * MT + p] = sqrtf(v * (1.0f / 3.0f));
            }
        } else {
            s_iy[p] = 0; s_ix[p] = 0; s_val[p] = 0;
            for (int k = 64; k < 71; k++) hA[k * MT + p] = 0.0f;
        }
    }
    __syncthreads();

    // ---- Phase 2: q_feat gather (all 256 threads; 16 channels each) ----
    {
        const int p = tid & (MT - 1);
        const int g = tid / MT;  // 0..3
        const int gp = p0 + p;
        const int b = (gp < P) ? (gp / (HQv * WQv)) : 0;
        const int iyc = s_iy[p], ixc = s_ix[p];
        const bool valid = s_val[p] != 0;
        const float* xb = x + (size_t)b * CCv * HFv * WFv + (size_t)iyc * WFv + ixc;
#pragma unroll
        for (int c = g * 16; c < g * 16 + 16; c++) {
            const float v = valid ? xb[(size_t)c * (HFv * WFv)] : 0.0f;
            hA[c * MT + p] = v;
        }
    }
    __syncthreads();

    // ---- Phase 3: MLP layers 0..3 (register-tiled fp32 GEMM) ----
    mlp_layer(W0, b0, hA, hB, wbuf, 71,  tid, true);
    mlp_layer(W1, b1, hB, hA, wbuf, 256, tid, true);
    mlp_layer(W2, b2, hA, hB, wbuf, 256, tid, true);
    mlp_layer(W3, b3, hB, hA, wbuf, 256, tid, true);

    // ---- Phase 4: final 256->3 layer + output write (threads 0..191) ----
    if (tid < MT * 3) {
        const int p = tid % MT;
        const int o = tid / MT;
        const int gp = p0 + p;
        if (gp < P) {
            float acc = 0.0f;
#pragma unroll 8
            for (int k = 0; k < 256; k++)
                acc = fmaf(hA[k * MT + p], W4[k * 3 + o], acc);
            acc += b4[o];
            const int b = gp / (HQv * WQv);
            const int rem = gp % (HQv * WQv);
            const int yq = rem / WQv;
            const int xq = rem % WQv;
            out[((size_t)(b * 3 + o) * HQv + yq) * WQv + xq] = acc;
        }
    }
}

extern "C" void kernel_launch(void* const* d_in, const int* in_sizes, int n_in,
                              void* d_out, int out_size)
{
    const float* x     = (const float*)d_in[0];
    const float* coord = (const float*)d_in[1];
    const float* cell  = (const float*)d_in[2];
    const float* lr    = (const float*)d_in[3];
    const float* W0    = (const float*)d_in[4];
    const float* b0    = (const float*)d_in[5];
    const float* W1    = (const float*)d_in[6];
    const float* b1    = (const float*)d_in[7];
    const float* W2    = (const float*)d_in[8];
    const float* b2    = (const float*)d_in[9];
    const float* W3    = (const float*)d_in[10];
    const float* b3    = (const float*)d_in[11];
    const float* W4    = (const float*)d_in[12];
    const float* b4    = (const float*)d_in[13];
    float* out = (float*)d_out;

    const int P = out_size / 3;                 // 589824 query points
    const int nblk = (P + MT - 1) / MT;         // 9216

    cudaFuncSetAttribute(liif_fused_kernel,
                         cudaFuncAttributeMaxDynamicSharedMemorySize, SMEM_BYTES);

    liif_fused_kernel<<<nblk, NTH, SMEM_BYTES>>>(
        x, coord, cell, lr, W0, b0, W1, b1, W2, b2, W3, b3, W4, b4, out, P);
}

// round 3
// speedup vs baseline: 2.6638x; 2.6638x over previous
#include <cuda_runtime.h>
#include <cuda_bf16.h>
#include <cstdint>

// ============================================================================
// LIIF sampler via mma.sync (HMMA bf16, standard PTX — no sm_103a features):
// gather -> A0 bf16 hi/lo in smem -> 4 layers of [128 x 256 x K] GEMM with
// 3-product bf16 split, fp32 register accumulators -> exact fp32 final layer.
// W pre-split into bf16 hi/lo blob by prep kernel; streamed via cp.async.
// ============================================================================

#define HQv 384
#define WQv 384
#define HFv 48
#define WFv 48

#define MT  128
#define NTH 256

// smem layout (bytes)
#define A_HI_OFF 0
#define A_LO_OFF (128 * 528)                 // 67584
#define WBUF_OFF (2 * 128 * 528)             // 135168
#define WPLANE   (32 * 528)                  // 16896
#define WBUF_SZ  (2 * WPLANE)                // 33792 (hi+lo)
#define BIAS_OFF (WBUF_OFF + 2 * WBUF_SZ)    // 202752
#define W4_OFF   (BIAS_OFF + 4096)           // 206848
#define B4_OFF   (W4_OFF + 3072)             // 209920
#define OACC_OFF (B4_OFF + 16)               // 209936
#define SMEM_TOTAL (OACC_OFF + 1536)         // 211472

// weight blob: per layer, hi plane [Kpad][256] bf16 then lo plane.
// Kpad: L0=96, L1..3=256. bases in bytes below.
__device__ __align__(128) unsigned char g_wblob[884736];
__constant__ int c_lbase[4] = {0, 98304, 360448, 622592};
__constant__ int c_kpad[4]  = {96, 256, 256, 256};

// ---------------------------------------------------------------------------
__device__ __forceinline__ uint32_t smem_u32(const void* p) {
    uint32_t a;
    asm("{ .reg .u64 t; cvta.to.shared.u64 t, %1; cvt.u32.u64 %0, t; }"
        : "=r"(a) : "l"(p));
    return a;
}
__device__ __forceinline__ void ldsm4(uint32_t& r0, uint32_t& r1, uint32_t& r2,
                                      uint32_t& r3, uint32_t a) {
    asm volatile("ldmatrix.sync.aligned.m8n8.x4.shared.b16 {%0,%1,%2,%3}, [%4];"
                 : "=r"(r0), "=r"(r1), "=r"(r2), "=r"(r3) : "r"(a));
}
__device__ __forceinline__ void ldsm4t(uint32_t& r0, uint32_t& r1, uint32_t& r2,
                                       uint32_t& r3, uint32_t a) {
    asm volatile("ldmatrix.sync.aligned.m8n8.x4.trans.shared.b16 {%0,%1,%2,%3}, [%4];"
                 : "=r"(r0), "=r"(r1), "=r"(r2), "=r"(r3) : "r"(a));
}
__device__ __forceinline__ void mma16816(float* d, uint32_t a0, uint32_t a1,
                                         uint32_t a2, uint32_t a3,
                                         uint32_t b0, uint32_t b1) {
    asm volatile(
        "mma.sync.aligned.m16n8k16.row.col.f32.bf16.bf16.f32 "
        "{%0,%1,%2,%3}, {%4,%5,%6,%7}, {%8,%9}, {%0,%1,%2,%3};"
        : "+f"(d[0]), "+f"(d[1]), "+f"(d[2]), "+f"(d[3])
        : "r"(a0), "r"(a1), "r"(a2), "r"(a3), "r"(b0), "r"(b1));
}
__device__ __forceinline__ void cpasync16(uint32_t dst, const void* src) {
    asm volatile("cp.async.cg.shared.global [%0], [%1], 16;"
                 :: "r"(dst), "l"(src) : "memory");
}
__device__ __forceinline__ void cp_commit() {
    asm volatile("cp.async.commit_group;" ::: "memory");
}

__device__ __forceinline__ void cvt2(float a, float b, uint32_t& hi, uint32_t& lo) {
    __nv_bfloat16 ah = __float2bfloat16(a), bh = __float2bfloat16(b);
    __nv_bfloat16 al = __float2bfloat16(a - __bfloat162float(ah));
    __nv_bfloat16 bl = __float2bfloat16(b - __bfloat162float(bh));
    hi = (uint32_t)__bfloat16_as_ushort(ah) | ((uint32_t)__bfloat16_as_ushort(bh) << 16);
    lo = (uint32_t)__bfloat16_as_ushort(al) | ((uint32_t)__bfloat16_as_ushort(bl) << 16);
}

// ---------------------------------------------------------------------------
// Prep: split W0..W3 fp32 -> bf16 hi/lo planes in g_wblob.
// grid = 864 blocks of 256 threads; block = one padded K-row, thread = n.
// ---------------------------------------------------------------------------
__global__ void liif_prep_kernel(const float* __restrict__ W0, const float* __restrict__ W1,
                                 const float* __restrict__ W2, const float* __restrict__ W3)
{
    const int row = blockIdx.x;       // 0..863
    const int n = threadIdx.x;        // 0..255
    int layer, k;
    if (row < 96) { layer = 0; k = row; }
    else { layer = 1 + (row - 96) / 256; k = (row - 96) & 255; }
    const float* W = (layer == 0) ? W0 : (layer == 1) ? W1 : (layer == 2) ? W2 : W3;
    const int Kl = (layer == 0) ? 71 : 256;
    const float val = (k < Kl) ? W[k * 256 + n] : 0.0f;
    __nv_bfloat16 hi = __float2bfloat16(val);
    __nv_bfloat16 lo = __float2bfloat16(val - __bfloat162float(hi));
    unsigned char* base = g_wblob + c_lbase[layer];
    *(unsigned short*)(base + (size_t)k * 512 + n * 2) = __bfloat16_as_ushort(hi);
    *(unsigned short*)(base + (size_t)c_kpad[layer] * 512 + (size_t)k * 512 + n * 2) =
        __bfloat16_as_ushort(lo);
}

// ---------------------------------------------------------------------------
__device__ __forceinline__ void issue_chunk(uint32_t sb, int tid,
                                            const unsigned char* lbase, int kpad,
                                            int c, int bsel)
{
    // 2 planes x 32 rows x 32 segs of 16B
#pragma unroll
    for (int it = 0; it < 8; it++) {
        const int i = tid + it * 256;
        const int pl = i >> 10;
        const int r = (i >> 5) & 31;
        const int s = i & 31;
        const unsigned char* src = lbase + (size_t)pl * ((size_t)kpad * 512)
                                 + (size_t)(c * 32 + r) * 512 + s * 16;
        const uint32_t dst = sb + WBUF_OFF + bsel * WBUF_SZ + pl * WPLANE + r * 528 + s * 16;
        cpasync16(dst, src);
    }
    cp_commit();
}

// ---------------------------------------------------------------------------
__global__ __launch_bounds__(NTH, 1)
void liif_hmma_kernel(
    const float* __restrict__ x, const float* __restrict__ coord,
    const float* __restrict__ cell, const float* __restrict__ lr,
    const float* __restrict__ b0, const float* __restrict__ b1,
    const float* __restrict__ b2, const float* __restrict__ b3,
    const float* __restrict__ W4, const float* __restrict__ b4,
    float* __restrict__ out)
{
    extern __shared__ __align__(16) char smem[];
    const uint32_t sb = smem_u32(smem);
    const int tid = threadIdx.x;
    const int lane = tid & 31;
    const int wid = tid >> 5;
    const int wm = wid & 3;   // 4 warps along M (32 rows each)
    const int wn = wid >> 2;  // 2 warps along N (128 cols each)

    float* bias_s = (float*)(smem + BIAS_OFF);
    float* w4_s   = (float*)(smem + W4_OFF);
    float* b4_s   = (float*)(smem + B4_OFF);
    float* oacc   = (float*)(smem + OACC_OFF);

    // stage biases + W4
    bias_s[tid] = b0[tid]; bias_s[256 + tid] = b1[tid];
    bias_s[512 + tid] = b2[tid]; bias_s[768 + tid] = b3[tid];
    for (int i = tid; i < 768; i += NTH) w4_s[i] = W4[i];
    if (tid < 3) b4_s[tid] = b4[tid];

    // ---- gather -> A0 (bf16 hi/lo, rows=points, cols=features, stride 528B) ----
    const int p  = tid & 127;
    const int gp = blockIdx.x * MT + p;
    const int b  = gp / (HQv * WQv);
    const int rem = gp % (HQv * WQv);
    const int yq = rem / WQv, xq = rem % WQv;
    const float gy = coord[((size_t)(b * HQv + yq) * WQv + xq) * 2 + 0];
    const float gx = coord[((size_t)(b * HQv + yq) * WQv + xq) * 2 + 1];

    float tx = __fmul_rn(__fadd_rn(__fmul_rn(__fadd_rn(gx, 1.0f), (float)WFv), -1.0f), 0.5f);
    float ty = __fmul_rn(__fadd_rn(__fmul_rn(__fadd_rn(gy, 1.0f), (float)HFv), -1.0f), 0.5f);
    const int ixn = (int)rintf(tx);
    const int iyn = (int)rintf(ty);
    const bool valid = (ixn >= 0) && (ixn < WFv) && (iyn >= 0) && (iyn < HFv);
    const int ixc = min(max(ixn, 0), WFv - 1);
    const int iyc = min(max(iyn, 0), HFv - 1);

    if (tid < 128) {
        const float* xb = x + (size_t)b * 64 * (HFv * WFv) + (size_t)iyc * WFv + ixc;
        char* rowp_hi = smem + (size_t)p * 528;
        char* rowp_lo = smem + A_LO_OFF + (size_t)p * 528;
#pragma unroll
        for (int k = 0; k < 32; k++) {
            const float f0 = valid ? xb[(size_t)(2 * k) * (HFv * WFv)] : 0.0f;
            const float f1 = valid ? xb[(size_t)(2 * k + 1) * (HFv * WFv)] : 0.0f;
            uint32_t hi, lo;
            cvt2(f0, f1, hi, lo);
            *(uint32_t*)(rowp_hi + k * 4) = hi;
            *(uint32_t*)(rowp_lo + k * 4) = lo;
        }
    } else {
        float qy = 0.0f, qx = 0.0f;
        if (valid) {
            qy = __fadd_rn(__fdiv_rn(__fadd_rn(__fmul_rn(2.0f, (float)iyc), 1.0f), (float)HFv), -1.0f);
            qx = __fadd_rn(__fdiv_rn(__fadd_rn(__fmul_rn(2.0f, (float)ixc), 1.0f), (float)WFv), -1.0f);
        }
        float vals[32];
#pragma unroll
        for (int i = 0; i < 32; i++) vals[i] = 0.0f;
        vals[0] = __fmul_rn(__fadd_rn(gy, -qy), (float)HFv);
        vals[1] = __fmul_rn(__fadd_rn(gx, -qx), (float)WFv);
        vals[2] = __fmul_rn(cell[b * 2 + 0], (float)HFv);
        vals[3] = __fmul_rn(cell[b * 2 + 1], (float)WFv);
        const float rx = 1.0f / (float)HFv, ry = 1.0f / (float)WFv;
        const float lo_c = -1.0f + 1e-6f, hi_c = 1.0f - 1e-6f;
        float s[3][4];
        int j = 0;
#pragma unroll
        for (int a = 0; a < 2; a++) {
#pragma unroll
            for (int c2 = 0; c2 < 2; c2++) {
                const float vx = a ? 1.0f : -1.0f;
                const float vy = c2 ? 1.0f : -1.0f;
                float cy = __fadd_rn(__fadd_rn(gy, __fmul_rn(vx, rx)), 1e-6f);
                float cx = __fadd_rn(__fadd_rn(gx, __fmul_rn(vy, ry)), 1e-6f);
                cy = fminf(fmaxf(cy, lo_c), hi_c);
                cx = fminf(fmaxf(cx, lo_c), hi_c);
                float fx = __fmul_rn(__fadd_rn(__fmul_rn(__fadd_rn(cx, 1.0f), (float)WFv), -1.0f), 0.5f);
                float fy = __fmul_rn(__fadd_rn(__fmul_rn(__fadd_rn(cy, 1.0f), (float)HFv), -1.0f), 0.5f);
                int jx = min(max((int)rintf(fx), 0), WFv - 1);
                int jy = min(max((int)rintf(fy), 0), HFv - 1);
#pragma unroll
                for (int ch = 0; ch < 3; ch++)
                    s[ch][j] = lr[((size_t)(b * 3 + ch) * HFv + jy) * WFv + jx];
                j++;
            }
        }
#pragma unroll
        for (int ch = 0; ch < 3; ch++) {
            const float m = 0.25f * (s[ch][0] + s[ch][1] + s[ch][2] + s[ch][3]);
            float v = 0.0f;
#pragma unroll
            for (int q = 0; q < 4; q++) { const float d = s[ch][q] - m; v += d * d; }
            vals[4 + ch] = sqrtf(v * (1.0f / 3.0f));
        }
        char* rowp_hi = smem + (size_t)p * 528 + 128;             // col 64 -> byte 128
        char* rowp_lo = smem + A_LO_OFF + (size_t)p * 528 + 128;
#pragma unroll
        for (int k = 0; k < 16; k++) {                            // cols 64..95
            uint32_t hi, lo;
            cvt2(vals[2 * k], vals[2 * k + 1], hi, lo);
            *(uint32_t*)(rowp_hi + k * 4) = hi;
            *(uint32_t*)(rowp_lo + k * 4) = lo;
        }
    }
    __syncthreads();

    // ---- 4 MMA layers ----
    float acc[2][16][4];
    const uint32_t aRowByte = (uint32_t)(wm * 32 + (lane & 15)) * 528 + (lane >> 4) * 16;
    const uint32_t bColByte = (uint32_t)(wn * 128 + (lane >> 4) * 8) * 2;
    const uint32_t bRowByte = (uint32_t)(lane & 15) * 528;

#pragma unroll 1
    for (int layer = 0; layer < 4; layer++) {
        const unsigned char* lbase = g_wblob + c_lbase[layer];
        const int kpad = (layer == 0) ? 96 : 256;
        const int nch = kpad >> 5;

#pragma unroll
        for (int mt = 0; mt < 2; mt++)
#pragma unroll
            for (int nt = 0; nt < 16; nt++)
#pragma unroll
                for (int e = 0; e < 4; e++) acc[mt][nt][e] = 0.0f;

        issue_chunk(sb, tid, lbase, kpad, 0, 0);

#pragma unroll 1
        for (int c = 0; c < nch; c++) {
            if (c + 1 < nch) {
                issue_chunk(sb, tid, lbase, kpad, c + 1, (c + 1) & 1);
                asm volatile("cp.async.wait_group 1;" ::: "memory");
            } else {
                asm volatile("cp.async.wait_group 0;" ::: "memory");
            }
            __syncthreads();

            const uint32_t wb = sb + WBUF_OFF + (c & 1) * WBUF_SZ;
#pragma unroll
            for (int kk = 0; kk < 2; kk++) {
                const uint32_t kByte = (uint32_t)(c * 32 + kk * 16) * 2;
                uint32_t ah[2][4], al[2][4];
#pragma unroll
                for (int mt = 0; mt < 2; mt++) {
                    const uint32_t aoff = aRowByte + (uint32_t)(mt * 16) * 528 + kByte;
                    ldsm4(ah[mt][0], ah[mt][1], ah[mt][2], ah[mt][3], sb + A_HI_OFF + aoff);
                    ldsm4(al[mt][0], al[mt][1], al[mt][2], al[mt][3], sb + A_LO_OFF + aoff);
                }
#pragma unroll
                for (int ng = 0; ng < 8; ng++) {
                    const uint32_t bo = bRowByte + (uint32_t)(kk * 16) * 528
                                      + bColByte + (uint32_t)(ng * 16) * 2;
                    uint32_t bh0, bh1, bh2, bh3;
                    ldsm4t(bh0, bh1, bh2, bh3, wb + bo);
#pragma unroll
                    for (int mt = 0; mt < 2; mt++) {
                        mma16816(acc[mt][2 * ng],     ah[mt][0], ah[mt][1], ah[mt][2], ah[mt][3], bh0, bh1);
                        mma16816(acc[mt][2 * ng + 1], ah[mt][0], ah[mt][1], ah[mt][2], ah[mt][3], bh2, bh3);
                        mma16816(acc[mt][2 * ng],     al[mt][0], al[mt][1], al[mt][2], al[mt][3], bh0, bh1);
                        mma16816(acc[mt][2 * ng + 1], al[mt][0], al[mt][1], al[mt][2], al[mt][3], bh2, bh3);
                    }
                    uint32_t bl0, bl1, bl2, bl3;
                    ldsm4t(bl0, bl1, bl2, bl3, wb + WPLANE + bo);
#pragma unroll
                    for (int mt = 0; mt < 2; mt++) {
                        mma16816(acc[mt][2 * ng],     ah[mt][0], ah[mt][1], ah[mt][2], ah[mt][3], bl0, bl1);
                        mma16816(acc[mt][2 * ng + 1], ah[mt][0], ah[mt][1], ah[mt][2], ah[mt][3], bl2, bl3);
                    }
                }
            }
            __syncthreads();
        }

        const float* bl_bias = bias_s + layer * 256;
        if (layer < 3) {
            // epilogue: relu(D + b) -> bf16 hi/lo, write A in place
#pragma unroll
            for (int mt = 0; mt < 2; mt++) {
#pragma unroll
                for (int nt = 0; nt < 16; nt++) {
                    const int r0 = wm * 32 + mt * 16 + (lane >> 2);
                    const int c0 = wn * 128 + nt * 8 + (lane & 3) * 2;
                    const float bb0 = bl_bias[c0], bb1 = bl_bias[c0 + 1];
                    const float h00 = fmaxf(acc[mt][nt][0] + bb0, 0.0f);
                    const float h01 = fmaxf(acc[mt][nt][1] + bb1, 0.0f);
                    const float h10 = fmaxf(acc[mt][nt][2] + bb0, 0.0f);
                    const float h11 = fmaxf(acc[mt][nt][3] + bb1, 0.0f);
                    uint32_t hi, lo;
                    cvt2(h00, h01, hi, lo);
                    *(uint32_t*)(smem + (size_t)r0 * 528 + c0 * 2) = hi;
                    *(uint32_t*)(smem + A_LO_OFF + (size_t)r0 * 528 + c0 * 2) = lo;
                    cvt2(h10, h11, hi, lo);
                    *(uint32_t*)(smem + (size_t)(r0 + 8) * 528 + c0 * 2) = hi;
                    *(uint32_t*)(smem + A_LO_OFF + (size_t)(r0 + 8) * 528 + c0 * 2) = lo;
                }
            }
            __syncthreads();
        } else {
            // final layer: out = relu(D + b3) @ W4 + b4 (exact fp32)
            for (int i = tid; i < 384; i += NTH) oacc[i] = 0.0f;
            __syncthreads();

            float sres[4][3];
#pragma unroll
            for (int i = 0; i < 4; i++)
#pragma unroll
                for (int o = 0; o < 3; o++) sres[i][o] = 0.0f;
#pragma unroll
            for (int nt = 0; nt < 16; nt++) {
#pragma unroll
                for (int e = 0; e < 2; e++) {
                    const int col = wn * 128 + nt * 8 + (lane & 3) * 2 + e;
                    const float bb = bl_bias[col];
                    const float w40 = w4_s[col * 3 + 0];
                    const float w41 = w4_s[col * 3 + 1];
                    const float w42 = w4_s[col * 3 + 2];
                    const float h0 = fmaxf(acc[0][nt][e] + bb, 0.0f);     // row r0
                    const float h1 = fmaxf(acc[0][nt][2 + e] + bb, 0.0f); // row r0+8
                    const float h2 = fmaxf(acc[1][nt][e] + bb, 0.0f);     // row r0+16
                    const float h3v = fmaxf(acc[1][nt][2 + e] + bb, 0.0f);// row r0+24
                    sres[0][0] = fmaf(h0, w40, sres[0][0]); sres[0][1] = fmaf(h0, w41, sres[0][1]); sres[0][2] = fmaf(h0, w42, sres[0][2]);
                    sres[1][0] = fmaf(h1, w40, sres[1][0]); sres[1][1] = fmaf(h1, w41, sres[1][1]); sres[1][2] = fmaf(h1, w42, sres[1][2]);
                    sres[2][0] = fmaf(h2, w40, sres[2][0]); sres[2][1] = fmaf(h2, w41, sres[2][1]); sres[2][2] = fmaf(h2, w42, sres[2][2]);
                    sres[3][0] = fmaf(h3v, w40, sres[3][0]); sres[3][1] = fmaf(h3v, w41, sres[3][1]); sres[3][2] = fmaf(h3v, w42, sres[3][2]);
                }
            }
            const int rbase = wm * 32 + (lane >> 2);
#pragma unroll
            for (int i = 0; i < 4; i++) {
                const int row = rbase + i * 8;
#pragma unroll
                for (int o = 0; o < 3; o++)
                    atomicAdd(&oacc[row * 3 + o], sres[i][o]);
            }
            __syncthreads();

            if (tid < 128) {
                const size_t base = (size_t)(b * 3) * (HQv * WQv) + (size_t)yq * WQv + xq;
                out[base]                            = oacc[tid * 3 + 0] + b4_s[0];
                out[base + (size_t)(HQv * WQv)]      = oacc[tid * 3 + 1] + b4_s[1];
                out[base + (size_t)(2 * HQv * WQv)]  = oacc[tid * 3 + 2] + b4_s[2];
            }
        }
    }
}

// ---------------------------------------------------------------------------
extern "C" void kernel_launch(void* const* d_in, const int* in_sizes, int n_in,
                              void* d_out, int out_size)
{
    const float* x     = (const float*)d_in[0];
    const float* coord = (const float*)d_in[1];
    const float* cell  = (const float*)d_in[2];
    const float* lr    = (const float*)d_in[3];
    const float* W0    = (const float*)d_in[4];
    const float* b0    = (const float*)d_in[5];
    const float* W1    = (const float*)d_in[6];
    const float* b1    = (const float*)d_in[7];
    const float* W2    = (const float*)d_in[8];
    const float* b2    = (const float*)d_in[9];
    const float* W3    = (const float*)d_in[10];
    const float* b3    = (const float*)d_in[11];
    const float* W4    = (const float*)d_in[12];
    const float* b4    = (const float*)d_in[13];
    float* out = (float*)d_out;

    liif_prep_kernel<<<864, 256>>>(W0, W1, W2, W3);

    const int P = out_size / 3;      // 589824
    const int nblk = P / MT;         // 4608

    cudaFuncSetAttribute(liif_hmma_kernel,
                         cudaFuncAttributeMaxDynamicSharedMemorySize, SMEM_TOTAL);
    liif_hmma_kernel<<<nblk, NTH, SMEM_TOTAL>>>(
        x, coord, cell, lr, b0, b1, b2, b3, W4, b4, out);
}